// round 2
// baseline (speedup 1.0000x reference)
#include <cuda_runtime.h>

// CTC forward scan: T=4096 steps, B=64 batches, P=512 positions (+pos 0), F=5 feats.
// One CTA per batch. 256 threads; thread i owns fwd positions 2i+1, 2i+2 in registers.
// Per step: neighbor fwd via __shfl_up; warp boundary via double-buffered smem slot;
// fwd[0] maintained redundantly in every thread (running sum of the stay feature).
// x staged in 128-step smem chunks, next chunk prefetched into registers.

#define T_STEPS 4096
#define BATCH 64
#define NFEAT 5
#define P_POS 512
#define NEG_LARGE (-1e30f)
#define CHUNK 128
#define PITCH 132            // CHUNK + 4: feature rows land in distinct smem banks
#define NCHUNK (T_STEPS / CHUNK)
#define NTHREADS 256
#define NWARPS (NTHREADS / 32)
#define CHUNK_ELEMS (CHUNK * NFEAT)   // 640
#define LDPT 3                        // ceil(640 / 256)

__device__ __forceinline__ float lae(float a, float b) {
    // logaddexp, stable: max + log1p(exp(min-max)). Handles -1e30 sentinels:
    // d is always <= 0; exp underflows cleanly; (-1e30)-(-1e30)=0 -> m+ln2 = -1e30 in fp32.
    float m = fmaxf(a, b);
    float d = fminf(a, b) - m;
    return m + __logf(1.0f + __expf(d));
}

__global__ void __launch_bounds__(NTHREADS, 1)
ctc_fwd_kernel(const float* __restrict__ x,
               const int*   __restrict__ seqs,
               const int*   __restrict__ seqlens,
               float*       __restrict__ out)
{
    const int b    = blockIdx.x;
    const int tid  = threadIdx.x;
    const int lane = tid & 31;
    const int w    = tid >> 5;

    __shared__ float xsm[2 * NFEAT * PITCH];   // double-buffered x chunk, [buf][feat][t]
    __shared__ float bnd[2][NWARPS];           // double-buffered warp-boundary fwd values
    __shared__ float ffin[P_POS + 1];          // final fwd vector for epilogue gather

    // Per-thread emit feature indices (constant over t): positions 2*tid+1, 2*tid+2
    // use seqs[b, 2*tid] and seqs[b, 2*tid+1].
    const int si0 = seqs[b * P_POS + 2 * tid];
    const int si1 = seqs[b * P_POS + 2 * tid + 1];
    const int ro0 = si0 * PITCH;
    const int ro1 = si1 * PITCH;

    float f0v   = NEG_LARGE;   // fwd[2*tid+1]
    float f1v   = NEG_LARGE;   // fwd[2*tid+2]
    float fzero = 0.0f;        // fwd[0], maintained identically by all threads

    if (tid < NWARPS) { bnd[0][tid] = NEG_LARGE; bnd[1][tid] = NEG_LARGE; }

    const float* xb = x + b * NFEAT;   // x[t*B*F + b*F + f]

    // ---- prologue: load chunk 0 into smem buffer 0 ----
    {
        #pragma unroll
        for (int k = 0; k < LDPT; ++k) {
            int idx = tid + k * NTHREADS;
            if (idx < CHUNK_ELEMS) {
                int tl = idx / NFEAT;
                int f  = idx - tl * NFEAT;
                xsm[f * PITCH + tl] = xb[tl * (BATCH * NFEAT) + f];
            }
        }
    }
    __syncthreads();

    int t = 0;
    for (int c = 0; c < NCHUNK; ++c) {
        // ---- prefetch next chunk into registers (LDG latency hidden by compute) ----
        float nv[LDPT];
        const bool more = (c + 1 < NCHUNK);
        if (more) {
            const int t0 = (c + 1) * CHUNK;
            #pragma unroll
            for (int k = 0; k < LDPT; ++k) {
                int idx = tid + k * NTHREADS;
                if (idx < CHUNK_ELEMS) {
                    int tl = idx / NFEAT;
                    int f  = idx - tl * NFEAT;
                    nv[k] = xb[(t0 + tl) * (BATCH * NFEAT) + f];
                }
            }
        }

        const float* xs = xsm + (c & 1) * (NFEAT * PITCH);

        #pragma unroll 4
        for (int tc = 0; tc < CHUNK; ++tc, ++t) {
            // emit + stay features for this step (broadcast / conflict-free LDS)
            float e0   = xs[ro0 + tc];
            float e1   = xs[ro1 + tc];
            float xstv = xs[4 * PITCH + tc];

            // left neighbor fwd value (old): intra-warp via shfl, cross-warp via smem
            float up = __shfl_up_sync(0xffffffffu, f1v, 1);
            float L  = up;
            if (lane == 0) L = (w == 0) ? fzero : bnd[(t & 1) ^ 1][w - 1];

            // two independent logaddexp updates (all inputs are step-(t-1) values)
            float n0 = lae(e0 + L,   xstv + f0v);
            float n1 = lae(e1 + f0v, xstv + f1v);

            fzero += xstv;          // fwd[0] update (uses old fzero above)
            f0v = n0;
            f1v = n1;

            if (lane == 31) bnd[t & 1][w] = n1;   // publish boundary for next step
            __syncthreads();
        }

        // ---- commit prefetched chunk to the other smem buffer ----
        if (more) {
            float* xd = xsm + ((c + 1) & 1) * (NFEAT * PITCH);
            #pragma unroll
            for (int k = 0; k < LDPT; ++k) {
                int idx = tid + k * NTHREADS;
                if (idx < CHUNK_ELEMS) {
                    int tl = idx / NFEAT;
                    int f  = idx - tl * NFEAT;
                    xd[f * PITCH + tl] = nv[k];
                }
            }
            __syncthreads();
        }
    }

    // ---- epilogue: gather fwd[seqlens[b]] ----
    ffin[2 * tid + 1] = f0v;
    ffin[2 * tid + 2] = f1v;
    if (tid == 0) ffin[0] = fzero;
    __syncthreads();
    if (tid == 0) {
        int sl = seqlens[b];
        out[b] = -ffin[sl] * (1.0f / (float)T_STEPS);
    }
}

extern "C" void kernel_launch(void* const* d_in, const int* in_sizes, int n_in,
                              void* d_out, int out_size)
{
    const float* x       = (const float*)d_in[0];
    const int*   seqs    = (const int*)  d_in[1];
    const int*   seqlens = (const int*)  d_in[2];
    float*       out     = (float*)      d_out;

    ctc_fwd_kernel<<<BATCH, NTHREADS>>>(x, seqs, seqlens, out);
}

// round 3
// speedup vs baseline: 1.0997x; 1.0997x over previous
#include <cuda_runtime.h>

// CTC forward scan, wavefront-pipelined across warps.
// T=4096 steps, B=64 batches (1 CTA each), P=512 positions (+pos 0), F=5.
// 128 threads = 4 warps; warp w owns positions [128w+1, 128(w+1)], 4 per lane.
// Time-skew: warp w processes 32-step chunk c at epoch e=c+w; boundary values
// flow warp->warp through double-buffered smem with ONE __syncthreads per epoch.
// Recurrence kept in log2 domain (raw ex2/lg2.approx). fwd[0] = running stay sum,
// maintained per-thread. x staged in an 8-slab smem ring, prefetched 1 chunk ahead.

#define T_STEPS 4096
#define BATCH 64
#define NFEAT 5
#define P_POS 512
#define NEG_LARGE (-1e30f)
#define K_EPOCH 32
#define NCHUNK (T_STEPS / K_EPOCH)        // 128
#define NTHREADS 128
#define NWARPS 4
#define NEPOCH (NCHUNK + NWARPS - 1)      // 131
#define PIT 33                            // feature-row pitch: 5 rows -> 5 distinct banks
#define SLABP 168                         // 5*33=165, padded
#define NSLAB 8
#define L2E 1.4426950408889634f
#define LN2 0.6931471805599453f

__device__ __forceinline__ float ex2f(float v){ float r; asm("ex2.approx.f32 %0,%1;" : "=f"(r) : "f"(v)); return r; }
__device__ __forceinline__ float lg2f(float v){ float r; asm("lg2.approx.f32 %0,%1;" : "=f"(r) : "f"(v)); return r; }

// logaddexp in log2 domain. Sentinel-safe: both ~-1e30 -> m+1 (== (f+ln2)*log2e);
// one -1e30 -> ex2 underflows to 0 -> lg2(1)=0 -> returns the finite side.
__device__ __forceinline__ float lae2(float a, float b) {
    float m = fmaxf(a, b);
    float d = -fabsf(a - b);
    return m + lg2f(1.0f + ex2f(d));
}

__global__ void __launch_bounds__(NTHREADS, 1)
ctc_fwd_kernel(const float* __restrict__ x,
               const int*   __restrict__ seqs,
               const int*   __restrict__ seqlens,
               float*       __restrict__ out)
{
    const int b    = blockIdx.x;
    const int tid  = threadIdx.x;
    const int lane = tid & 31;
    const int w    = tid >> 5;

    __shared__ float xsm[NSLAB * SLABP];            // x ring: [slab][feat][t], pitch 33
    __shared__ float bnd[2][NWARPS][K_EPOCH + 1];   // boundary values, per write-epoch parity
    __shared__ float ffin[P_POS + 1];               // final fwd for epilogue gather

    // Lane owns positions pbase+1..pbase+4; emits use seqs[b, pbase+j].
    const int pbase = (w << 7) + (lane << 2);
    const int4 si = *reinterpret_cast<const int4*>(seqs + b * P_POS + pbase);
    const int ro0 = si.x * PIT, ro1 = si.y * PIT, ro2 = si.z * PIT, ro3 = si.w * PIT;

    float f0 = NEG_LARGE, f1 = NEG_LARGE, f2 = NEG_LARGE, f3 = NEG_LARGE;
    float fzero = 0.0f;   // log2-domain fwd[0]; each warp tracks it for its own timeline

    const float* xb = x + b * NFEAT;  // x[t*B*F + b*F + f]

    // init boundary buffers
    for (int i = tid; i < 2 * NWARPS * (K_EPOCH + 1); i += NTHREADS)
        (&bnd[0][0][0])[i] = NEG_LARGE;

    // prologue: chunk 0 -> slab 0   (idx = f*32 + t_local)
    {
        int f = tid >> 5, tl = tid & 31;
        xsm[f * PIT + tl] = xb[tl * (BATCH * NFEAT) + f];
        if (tid < NFEAT * K_EPOCH - NTHREADS) {
            int idx = tid + NTHREADS; int f2i = idx >> 5, tl2 = idx & 31;
            xsm[f2i * PIT + tl2] = xb[tl2 * (BATCH * NFEAT) + f2i];
        }
    }
    __syncthreads();

    for (int e = 0; e < NEPOCH; ++e) {
        const int  c     = e - w;
        const bool valid = (c >= 0) && (c < NCHUNK);
        const int  par   = e & 1;

        // prefetch chunk e+1 into registers (latency hidden under the 32-step compute)
        float nv0 = 0.f, nv1 = 0.f;
        const bool pf = (e + 1) < NCHUNK;
        if (pf) {
            const int t0 = (e + 1) * K_EPOCH;
            int f = tid >> 5, tl = tid & 31;
            nv0 = xb[(t0 + tl) * (BATCH * NFEAT) + f];
            if (tid < NFEAT * K_EPOCH - NTHREADS) {
                int idx = tid + NTHREADS; int f2i = idx >> 5, tl2 = idx & 31;
                nv1 = xb[(t0 + tl2 * 0 + tl2) * 0 + (t0 + tl2) * (BATCH * NFEAT) + f2i]; // (kept simple below)
            }
        }
        // NOTE: the line above is rewritten correctly here to avoid any doubt:
        if (pf && tid < NFEAT * K_EPOCH - NTHREADS) {
            const int t0 = (e + 1) * K_EPOCH;
            int idx = tid + NTHREADS; int f2i = idx >> 5, tl2 = idx & 31;
            nv1 = xb[(t0 + tl2) * (BATCH * NFEAT) + f2i];
        }

        if (valid) {
            const float* xs = xsm + (c & (NSLAB - 1)) * SLABP;
            const float* bR = bnd[par ^ 1][(w > 0) ? (w - 1) : 0];
            float*       bW = &bnd[par][w][0];

            if (lane == 31) bW[0] = f3;   // carry-in boundary (fwd before this chunk)

            #pragma unroll 8
            for (int k = 0; k < K_EPOCH; ++k) {
                float stv = xs[4 * PIT + k];
                float e0v = xs[ro0 + k];
                float e1v = xs[ro1 + k];
                float e2v = xs[ro2 + k];
                float e3v = xs[ro3 + k];
                float bv  = bR[k];
                float s2  = stv * L2E;

                float up = __shfl_up_sync(0xffffffffu, f3, 1);
                float L  = up;
                if (lane == 0) L = (w == 0) ? fzero : bv;

                float a0 = fmaf(e0v, L2E, L);
                float a1 = fmaf(e1v, L2E, f0);
                float a2 = fmaf(e2v, L2E, f1);
                float a3 = fmaf(e3v, L2E, f2);
                float b0 = s2 + f0;
                float b1 = s2 + f1;
                float b2 = s2 + f2;
                float b3 = s2 + f3;

                f0 = lae2(a0, b0);
                f1 = lae2(a1, b1);
                f2 = lae2(a2, b2);
                f3 = lae2(a3, b3);
                fzero += s2;

                if (lane == 31 && k < K_EPOCH - 1) bW[k + 1] = f3;
            }
        }

        // commit prefetched chunk to its ring slab
        if (pf) {
            float* xd = xsm + ((e + 1) & (NSLAB - 1)) * SLABP;
            int f = tid >> 5, tl = tid & 31;
            xd[f * PIT + tl] = nv0;
            if (tid < NFEAT * K_EPOCH - NTHREADS) {
                int idx = tid + NTHREADS; int f2i = idx >> 5, tl2 = idx & 31;
                xd[f2i * PIT + tl2] = nv1;
            }
        }
        __syncthreads();
    }

    // epilogue: gather fwd[seqlens[b]]
    ffin[pbase + 1] = f0;
    ffin[pbase + 2] = f1;
    ffin[pbase + 3] = f2;
    ffin[pbase + 4] = f3;
    if (tid == 0) ffin[0] = fzero;
    __syncthreads();
    if (tid == 0) {
        int sl = seqlens[b];
        out[b] = -ffin[sl] * (LN2 / (float)T_STEPS);   // log2 -> ln, normalize
    }
}

extern "C" void kernel_launch(void* const* d_in, const int* in_sizes, int n_in,
                              void* d_out, int out_size)
{
    const float* x       = (const float*)d_in[0];
    const int*   seqs    = (const int*)  d_in[1];
    const int*   seqlens = (const int*)  d_in[2];
    float*       out     = (float*)      d_out;

    ctc_fwd_kernel<<<BATCH, NTHREADS>>>(x, seqs, seqlens, out);
}

// round 7
// speedup vs baseline: 1.9487x; 1.7720x over previous
#include <cuda_runtime.h>

// CTC forward scan split at T/2: CTA pairs per batch run the forward half
// (t=0..2047) and the mirrored backward half (t=4095..2048) concurrently;
// a tiny combine kernel does out = -LSE_m(F[m]+B[m]) * ln2 / T.
// Each half is R3's verified wavefront log2-domain kernel:
// 4 warps, 32-step chunks, skewed; lane owns 4 positions; 1 barrier/epoch.

#define T_STEPS   4096
#define T_HALF    2048
#define BATCH     64
#define NFEAT     5
#define P_POS     512
#define NEG_LARGE (-1e30f)
#define K_EPOCH   32
#define NCHUNK    (T_HALF / K_EPOCH)      // 64
#define NTHREADS  128
#define NWARPS    4
#define NEPOCH    (NCHUNK + NWARPS - 1)   // 67
#define PIT       33
#define SLABP     168
#define NSLAB     8
#define L2E       1.4426950408889634f
#define LN2F      0.6931471805599453f

__device__ float g_scrF[BATCH * (P_POS + 1)];
__device__ float g_scrB[BATCH * (P_POS + 1)];

__device__ __forceinline__ float ex2f(float v){ float r; asm("ex2.approx.f32 %0,%1;" : "=f"(r) : "f"(v)); return r; }
__device__ __forceinline__ float lg2f(float v){ float r; asm("lg2.approx.f32 %0,%1;" : "=f"(r) : "f"(v)); return r; }

__device__ __forceinline__ float lae2(float a, float b) {
    float m = fmaxf(a, b);
    float d = -fabsf(a - b);
    return m + lg2f(1.0f + ex2f(d));
}

__global__ void __launch_bounds__(NTHREADS, 1)
ctc_half_kernel(const float* __restrict__ x,
                const int*   __restrict__ seqs,
                const int*   __restrict__ seqlens)
{
    const bool fwdDir = (blockIdx.x & 1) == 0;
    const int  b      = blockIdx.x >> 1;
    const int  tid    = threadIdx.x;
    const int  lane   = tid & 31;
    const int  w      = tid >> 5;

    __shared__ float xsm[NSLAB * SLABP];            // x chunk ring: [slab][feat][t], *L2E
    __shared__ float bnd[2][NWARPS][K_EPOCH + 1];   // warp-boundary values per epoch parity

    // Emit feature rows. fwd: position p uses seqs[p-1]. bwd (q = P-m): q uses seqs[P-q].
    const int pb = (w << 7) + (lane << 2);          // owned positions pb+1 .. pb+4
    int si0, si1, si2, si3;
    if (fwdDir) {
        const int4 si = *reinterpret_cast<const int4*>(seqs + b * P_POS + pb);
        si0 = si.x; si1 = si.y; si2 = si.z; si3 = si.w;
    } else {
        const int* sp = seqs + b * P_POS;
        si0 = sp[P_POS - 1 - pb];
        si1 = sp[P_POS - 2 - pb];
        si2 = sp[P_POS - 3 - pb];
        si3 = sp[P_POS - 4 - pb];
    }
    const int ro0 = si0 * PIT, ro1 = si1 * PIT, ro2 = si2 * PIT, ro3 = si3 * PIT;

    // init: fwd -> delta at position 0 (fz channel); bwd -> delta at q0 = P - seqlens[b]
    const int q0 = P_POS - seqlens[b];
    float f0, f1, f2, f3, fz;
    if (fwdDir) {
        f0 = f1 = f2 = f3 = NEG_LARGE; fz = 0.0f;
    } else {
        f0 = (pb + 1 == q0) ? 0.f : NEG_LARGE;
        f1 = (pb + 2 == q0) ? 0.f : NEG_LARGE;
        f2 = (pb + 3 == q0) ? 0.f : NEG_LARGE;
        f3 = (pb + 4 == q0) ? 0.f : NEG_LARGE;
        fz = (q0 == 0) ? 0.f : NEG_LARGE;
    }

    const float* xb = x + b * NFEAT;   // x[t*B*F + b*F + f]
    const int    TB = BATCH * NFEAT;

    for (int i = tid; i < 2 * NWARPS * (K_EPOCH + 1); i += NTHREADS)
        (&bnd[0][0][0])[i] = NEG_LARGE;

    // stage chunk 0 (already scaled by L2E); t-map: fwd s -> s, bwd s -> T-1-s
    {
        int f = tid >> 5, tl = tid & 31;
        int t = fwdDir ? tl : (T_STEPS - 1 - tl);
        xsm[f * PIT + tl] = xb[t * TB + f] * L2E;
        if (tid < NFEAT * K_EPOCH - NTHREADS) {
            int idx = tid + NTHREADS; int f2i = idx >> 5, tl2 = idx & 31;
            int t2 = fwdDir ? tl2 : (T_STEPS - 1 - tl2);
            xsm[f2i * PIT + tl2] = xb[t2 * TB + f2i] * L2E;
        }
    }
    __syncthreads();

    int t = 0;
    for (int e = 0; e < NEPOCH; ++e) {
        const int  c     = e - w;
        const bool valid = (c >= 0) && (c < NCHUNK);

        // prefetch chunk e+1 into registers
        float nv0 = 0.f, nv1 = 0.f;
        const bool pf = (e + 1) < NCHUNK;
        if (pf) {
            const int s0 = (e + 1) * K_EPOCH;
            int f = tid >> 5, tl = tid & 31;
            int tg = fwdDir ? (s0 + tl) : (T_STEPS - 1 - (s0 + tl));
            nv0 = xb[tg * TB + f] * L2E;
            if (tid < NFEAT * K_EPOCH - NTHREADS) {
                int idx = tid + NTHREADS; int f2i = idx >> 5, tl2 = idx & 31;
                int tg2 = fwdDir ? (s0 + tl2) : (T_STEPS - 1 - (s0 + tl2));
                nv1 = xb[tg2 * TB + f2i] * L2E;
            }
        }

        if (valid) {
            const float* xs = xsm + (c & (NSLAB - 1)) * SLABP;
            const float* bR = bnd[(e & 1) ^ 1][(w > 0) ? (w - 1) : 0];
            float*       bW = &bnd[e & 1][w][0];

            if (lane == 31) bW[0] = f3;   // carry-in boundary

            #pragma unroll 8
            for (int k = 0; k < K_EPOCH; ++k) {
                float s2  = xs[4 * PIT + k];   // stay (log2)
                float e0v = xs[ro0 + k];
                float e1v = xs[ro1 + k];
                float e2v = xs[ro2 + k];
                float e3v = xs[ro3 + k];
                float bv  = bR[k];

                float up = __shfl_up_sync(0xffffffffu, f3, 1);
                float L  = up;
                if (lane == 0) L = (w == 0) ? fz : bv;

                float a0 = e0v + L;
                float a1 = e1v + f0;
                float a2 = e2v + f1;
                float a3 = e3v + f2;
                float b0 = s2 + f0;
                float b1 = s2 + f1;
                float b2 = s2 + f2;
                float b3 = s2 + f3;

                f0 = lae2(a0, b0);
                f1 = lae2(a1, b1);
                f2 = lae2(a2, b2);
                f3 = lae2(a3, b3);
                fz += s2;

                if (lane == 31 && k < K_EPOCH - 1) bW[k + 1] = f3;
            }
            t += K_EPOCH;
        }

        if (pf) {
            float* xd = xsm + ((e + 1) & (NSLAB - 1)) * SLABP;
            int f = tid >> 5, tl = tid & 31;
            xd[f * PIT + tl] = nv0;
            if (tid < NFEAT * K_EPOCH - NTHREADS) {
                int idx = tid + NTHREADS; int f2i = idx >> 5, tl2 = idx & 31;
                xd[f2i * PIT + tl2] = nv1;
            }
        }
        __syncthreads();
    }

    // write half-result to scratch. fwd: index = position. bwd: index = m = P - q.
    float* scr = fwdDir ? (g_scrF + b * (P_POS + 1)) : (g_scrB + b * (P_POS + 1));
    if (fwdDir) {
        scr[pb + 1] = f0; scr[pb + 2] = f1; scr[pb + 3] = f2; scr[pb + 4] = f3;
        if (tid == 0) scr[0] = fz;
    } else {
        scr[P_POS - (pb + 1)] = f0;
        scr[P_POS - (pb + 2)] = f1;
        scr[P_POS - (pb + 3)] = f2;
        scr[P_POS - (pb + 4)] = f3;
        if (tid == 0) scr[P_POS] = fz;   // q=0 -> m=P
    }
}

__global__ void __launch_bounds__(NTHREADS)
ctc_combine_kernel(float* __restrict__ out)
{
    const int b   = blockIdx.x;
    const int tid = threadIdx.x;
    const int lane = tid & 31;
    const int w    = tid >> 5;
    __shared__ float red[NWARPS];

    const float* F = g_scrF + b * (P_POS + 1);
    const float* B = g_scrB + b * (P_POS + 1);

    // pass 1: max of v = F + B
    float vm = -3e38f;
    float v[5];
    int   nv = 0;
    for (int p = tid; p <= P_POS; p += NTHREADS) {
        float t = F[p] + B[p];
        v[nv++] = t;
        vm = fmaxf(vm, t);
    }
    #pragma unroll
    for (int off = 16; off; off >>= 1)
        vm = fmaxf(vm, __shfl_xor_sync(0xffffffffu, vm, off));
    if (lane == 0) red[w] = vm;
    __syncthreads();
    vm = fmaxf(fmaxf(red[0], red[1]), fmaxf(red[2], red[3]));

    // pass 2: sum 2^(v - vm)
    float s = 0.f;
    for (int i = 0; i < nv; ++i) s += ex2f(v[i] - vm);
    #pragma unroll
    for (int off = 16; off; off >>= 1)
        s += __shfl_xor_sync(0xffffffffu, s, off);
    __syncthreads();
    if (lane == 0) red[w] = s;
    __syncthreads();
    if (tid == 0) {
        float st = red[0] + red[1] + red[2] + red[3];
        float lse = vm + lg2f(st);
        out[b] = -lse * (LN2F / (float)T_STEPS);
    }
}

extern "C" void kernel_launch(void* const* d_in, const int* in_sizes, int n_in,
                              void* d_out, int out_size)
{
    const float* x       = (const float*)d_in[0];
    const int*   seqs    = (const int*)  d_in[1];
    const int*   seqlens = (const int*)  d_in[2];
    float*       out     = (float*)      d_out;

    ctc_half_kernel<<<2 * BATCH, NTHREADS>>>(x, seqs, seqlens);
    ctc_combine_kernel<<<BATCH, NTHREADS>>>(out);
}

// round 8
// speedup vs baseline: 2.1360x; 1.0961x over previous
#include <cuda_runtime.h>

// CTC forward scan split at T/2 (fwd half + mirrored bwd half on separate CTAs),
// combine = -LSE_m(F[m]+B[m]) * ln2 / T.
// Each half: 256 threads = 8 warps (2/SMSP), wavefront-skewed by 32-step chunks;
// lane owns 2 consecutive positions (warp owns 64); log2-domain logaddexp via
// raw ex2/lg2.approx; 1 barrier per epoch. 2 warps/SMSP hide the lae chain
// latency, pushing the kernel onto the MUFU rt floor (~64 cyc/step).

#define T_STEPS   4096
#define T_HALF    2048
#define BATCH     64
#define NFEAT     5
#define P_POS     512
#define NEG_LARGE (-1e30f)
#define K_EPOCH   32
#define NCHUNK    (T_HALF / K_EPOCH)      // 64
#define NTHREADS  256
#define NWARPS    8
#define NEPOCH    (NCHUNK + NWARPS - 1)   // 71
#define PIT       33
#define SLABP     168
#define NSLAB     16                      // ring depth > skew(8)+prefetch(1)
#define L2E       1.4426950408889634f
#define LN2F      0.6931471805599453f

__device__ float g_scrF[BATCH * (P_POS + 1)];
__device__ float g_scrB[BATCH * (P_POS + 1)];

__device__ __forceinline__ float ex2f(float v){ float r; asm("ex2.approx.f32 %0,%1;" : "=f"(r) : "f"(v)); return r; }
__device__ __forceinline__ float lg2f(float v){ float r; asm("lg2.approx.f32 %0,%1;" : "=f"(r) : "f"(v)); return r; }

__device__ __forceinline__ float lae2(float a, float b) {
    float m = fmaxf(a, b);
    float d = -fabsf(a - b);
    return m + lg2f(1.0f + ex2f(d));
}

__global__ void __launch_bounds__(NTHREADS, 1)
ctc_half_kernel(const float* __restrict__ x,
                const int*   __restrict__ seqs,
                const int*   __restrict__ seqlens)
{
    const bool fwdDir = (blockIdx.x & 1) == 0;
    const int  b      = blockIdx.x >> 1;
    const int  tid    = threadIdx.x;
    const int  lane   = tid & 31;
    const int  w      = tid >> 5;

    __shared__ float xsm[NSLAB * SLABP];            // x chunk ring: [slab][feat][t], *L2E
    __shared__ float bnd[2][NWARPS][K_EPOCH + 1];   // warp-boundary values per epoch parity

    // Warp owns positions [64w+1, 64w+64]; lane owns pb+1, pb+2.
    const int pb = (w << 6) + (lane << 1);
    int si0, si1;
    if (fwdDir) {
        const int2 si = *reinterpret_cast<const int2*>(seqs + b * P_POS + pb);
        si0 = si.x; si1 = si.y;
    } else {
        const int* sp = seqs + b * P_POS;
        si0 = sp[P_POS - 1 - pb];
        si1 = sp[P_POS - 2 - pb];
    }
    const int ro0 = si0 * PIT, ro1 = si1 * PIT;

    // init: fwd -> delta at position 0 (fz channel); bwd -> delta at q0 = P - seqlens[b]
    const int q0 = P_POS - seqlens[b];
    float f0, f1, fz;
    if (fwdDir) {
        f0 = f1 = NEG_LARGE; fz = 0.0f;
    } else {
        f0 = (pb + 1 == q0) ? 0.f : NEG_LARGE;
        f1 = (pb + 2 == q0) ? 0.f : NEG_LARGE;
        fz = (q0 == 0) ? 0.f : NEG_LARGE;
    }

    const float* xb = x + b * NFEAT;   // x[t*B*F + b*F + f]
    const int    TB = BATCH * NFEAT;

    for (int i = tid; i < 2 * NWARPS * (K_EPOCH + 1); i += NTHREADS)
        (&bnd[0][0][0])[i] = NEG_LARGE;

    // stage chunk 0 (scaled by L2E); t-map: fwd s -> s, bwd s -> T-1-s
    if (tid < NFEAT * K_EPOCH) {
        int f = tid >> 5, tl = tid & 31;
        int t = fwdDir ? tl : (T_STEPS - 1 - tl);
        xsm[f * PIT + tl] = xb[t * TB + f] * L2E;
    }
    __syncthreads();

    for (int e = 0; e < NEPOCH; ++e) {
        const int  c     = e - w;
        const bool valid = (c >= 0) && (c < NCHUNK);

        // prefetch chunk e+1 into registers
        float nv0 = 0.f;
        const bool pf = (e + 1) < NCHUNK;
        if (pf && tid < NFEAT * K_EPOCH) {
            const int s0 = (e + 1) * K_EPOCH;
            int f = tid >> 5, tl = tid & 31;
            int tg = fwdDir ? (s0 + tl) : (T_STEPS - 1 - (s0 + tl));
            nv0 = xb[tg * TB + f] * L2E;
        }

        if (valid) {
            const float* xs = xsm + (c & (NSLAB - 1)) * SLABP;
            const float* bR = bnd[(e & 1) ^ 1][(w > 0) ? (w - 1) : 0];
            float*       bW = &bnd[e & 1][w][0];

            if (lane == 31) bW[0] = f1;   // carry-in boundary

            #pragma unroll 8
            for (int k = 0; k < K_EPOCH; ++k) {
                float s2  = xs[4 * PIT + k];   // stay (log2)
                float e0v = xs[ro0 + k];
                float e1v = xs[ro1 + k];
                float bv  = bR[k];

                float up = __shfl_up_sync(0xffffffffu, f1, 1);
                float L  = up;
                if (lane == 0) L = (w == 0) ? fz : bv;

                float a0 = e0v + L;
                float a1 = e1v + f0;
                float b0 = s2 + f0;
                float b1 = s2 + f1;

                f0 = lae2(a0, b0);
                f1 = lae2(a1, b1);
                fz += s2;

                if (lane == 31 && k < K_EPOCH - 1) bW[k + 1] = f1;
            }
        }

        if (pf && tid < NFEAT * K_EPOCH) {
            float* xd = xsm + ((e + 1) & (NSLAB - 1)) * SLABP;
            int f = tid >> 5, tl = tid & 31;
            xd[f * PIT + tl] = nv0;
        }
        __syncthreads();
    }

    // write half-result to scratch. fwd: index = position. bwd: index = m = P - q.
    float* scr = fwdDir ? (g_scrF + b * (P_POS + 1)) : (g_scrB + b * (P_POS + 1));
    if (fwdDir) {
        scr[pb + 1] = f0; scr[pb + 2] = f1;
        if (tid == 0) scr[0] = fz;
    } else {
        scr[P_POS - (pb + 1)] = f0;
        scr[P_POS - (pb + 2)] = f1;
        if (tid == 0) scr[P_POS] = fz;   // q=0 -> m=P
    }
}

__global__ void __launch_bounds__(128)
ctc_combine_kernel(float* __restrict__ out)
{
    const int b    = blockIdx.x;
    const int tid  = threadIdx.x;
    const int lane = tid & 31;
    const int w    = tid >> 5;
    __shared__ float red[4];

    const float* F = g_scrF + b * (P_POS + 1);
    const float* B = g_scrB + b * (P_POS + 1);

    float vm = -3e38f;
    float v[5];
    int   nv = 0;
    for (int p = tid; p <= P_POS; p += 128) {
        float t = F[p] + B[p];
        v[nv++] = t;
        vm = fmaxf(vm, t);
    }
    #pragma unroll
    for (int off = 16; off; off >>= 1)
        vm = fmaxf(vm, __shfl_xor_sync(0xffffffffu, vm, off));
    if (lane == 0) red[w] = vm;
    __syncthreads();
    vm = fmaxf(fmaxf(red[0], red[1]), fmaxf(red[2], red[3]));

    float s = 0.f;
    for (int i = 0; i < nv; ++i) s += ex2f(v[i] - vm);
    #pragma unroll
    for (int off = 16; off; off >>= 1)
        s += __shfl_xor_sync(0xffffffffu, s, off);
    __syncthreads();
    if (lane == 0) red[w] = s;
    __syncthreads();
    if (tid == 0) {
        float st = red[0] + red[1] + red[2] + red[3];
        float lse = vm + lg2f(st);
        out[b] = -lse * (LN2F / (float)T_STEPS);
    }
}

extern "C" void kernel_launch(void* const* d_in, const int* in_sizes, int n_in,
                              void* d_out, int out_size)
{
    const float* x       = (const float*)d_in[0];
    const int*   seqs    = (const int*)  d_in[1];
    const int*   seqlens = (const int*)  d_in[2];
    float*       out     = (float*)      d_out;

    ctc_half_kernel<<<2 * BATCH, NTHREADS>>>(x, seqs, seqlens);
    ctc_combine_kernel<<<BATCH, 128>>>(out);
}

// round 9
// speedup vs baseline: 2.2005x; 1.0302x over previous
#include <cuda_runtime.h>

// CTC forward scan split at T/2 (fwd half + mirrored bwd half on separate CTAs),
// combine = -LSE_m(F[m]+B[m]) * ln2 / T.
// Each half: 256 threads = 8 warps, wavefront-skewed by 32-step chunks;
// lane owns 2 consecutive positions; log2-domain logaddexp where the
// log2(1+y) term is a degree-5 polynomial (single MUFU per lae instead of two),
// cutting both the serial dependency chain and MUFU queue contention.

#define T_STEPS   4096
#define T_HALF    2048
#define BATCH     64
#define NFEAT     5
#define P_POS     512
#define NEG_LARGE (-1e30f)
#define K_EPOCH   32
#define NCHUNK    (T_HALF / K_EPOCH)      // 64
#define NTHREADS  256
#define NWARPS    8
#define NEPOCH    (NCHUNK + NWARPS - 1)   // 71
#define PIT       33
#define SLABP     168
#define NSLAB     16
#define L2E       1.4426950408889634f
#define LN2F      0.6931471805599453f

__device__ float g_scrF[BATCH * (P_POS + 1)];
__device__ float g_scrB[BATCH * (P_POS + 1)];

__device__ __forceinline__ float ex2f(float v){ float r; asm("ex2.approx.f32 %0,%1;" : "=f"(r) : "f"(v)); return r; }
__device__ __forceinline__ float lg2f(float v){ float r; asm("lg2.approx.f32 %0,%1;" : "=f"(r) : "f"(v)); return r; }

// log2(1+y) on y in [0,1], degree-5, Chebyshev-economized Taylor of log2(3+u)
// at u=2y-1; endpoint-centered. Max abs err ~5e-5.
__device__ __forceinline__ float lg2p1(float y) {
    float u = fmaf(2.0f, y, -1.0f);
    float p = fmaf(u, 0.00135227f, -0.0049475038f);
    p = fmaf(u, p,  0.0177286f);
    p = fmaf(u, p, -0.0799641965f);
    p = fmaf(u, p,  0.4809086f);
    p = fmaf(u, p,  0.5849121935f);
    return p;
}

// logaddexp in log2 domain, single-MUFU version.
// d <= 0 always; ex2 underflow -> y=0 -> p ~ 1e-5 (negligible); d=0 -> p ~ 1.
__device__ __forceinline__ float lae2(float a, float b) {
    float m = fmaxf(a, b);
    float d = -fabsf(a - b);
    return m + lg2p1(ex2f(d));
}

__global__ void __launch_bounds__(NTHREADS, 1)
ctc_half_kernel(const float* __restrict__ x,
                const int*   __restrict__ seqs,
                const int*   __restrict__ seqlens)
{
    const bool fwdDir = (blockIdx.x & 1) == 0;
    const int  b      = blockIdx.x >> 1;
    const int  tid    = threadIdx.x;
    const int  lane   = tid & 31;
    const int  w      = tid >> 5;

    __shared__ float xsm[NSLAB * SLABP];            // x chunk ring: [slab][feat][t], *L2E
    __shared__ float bnd[2][NWARPS][K_EPOCH + 1];   // warp-boundary values per epoch parity

    // Warp owns positions [64w+1, 64w+64]; lane owns pb+1, pb+2.
    const int pb = (w << 6) + (lane << 1);
    int si0, si1;
    if (fwdDir) {
        const int2 si = *reinterpret_cast<const int2*>(seqs + b * P_POS + pb);
        si0 = si.x; si1 = si.y;
    } else {
        const int* sp = seqs + b * P_POS;
        si0 = sp[P_POS - 1 - pb];
        si1 = sp[P_POS - 2 - pb];
    }
    const int ro0 = si0 * PIT, ro1 = si1 * PIT;

    // init: fwd -> delta at position 0 (fz channel); bwd -> delta at q0 = P - seqlens[b]
    const int q0 = P_POS - seqlens[b];
    float f0, f1, fz;
    if (fwdDir) {
        f0 = f1 = NEG_LARGE; fz = 0.0f;
    } else {
        f0 = (pb + 1 == q0) ? 0.f : NEG_LARGE;
        f1 = (pb + 2 == q0) ? 0.f : NEG_LARGE;
        fz = (q0 == 0) ? 0.f : NEG_LARGE;
    }

    const float* xb = x + b * NFEAT;   // x[t*B*F + b*F + f]
    const int    TB = BATCH * NFEAT;

    for (int i = tid; i < 2 * NWARPS * (K_EPOCH + 1); i += NTHREADS)
        (&bnd[0][0][0])[i] = NEG_LARGE;

    // stage chunk 0 (scaled by L2E); t-map: fwd s -> s, bwd s -> T-1-s
    if (tid < NFEAT * K_EPOCH) {
        int f = tid >> 5, tl = tid & 31;
        int t = fwdDir ? tl : (T_STEPS - 1 - tl);
        xsm[f * PIT + tl] = xb[t * TB + f] * L2E;
    }
    __syncthreads();

    for (int e = 0; e < NEPOCH; ++e) {
        const int  c     = e - w;
        const bool valid = (c >= 0) && (c < NCHUNK);

        // prefetch chunk e+1 into registers
        float nv0 = 0.f;
        const bool pf = (e + 1) < NCHUNK;
        if (pf && tid < NFEAT * K_EPOCH) {
            const int s0 = (e + 1) * K_EPOCH;
            int f = tid >> 5, tl = tid & 31;
            int tg = fwdDir ? (s0 + tl) : (T_STEPS - 1 - (s0 + tl));
            nv0 = xb[tg * TB + f] * L2E;
        }

        if (valid) {
            const float* xs = xsm + (c & (NSLAB - 1)) * SLABP;
            const float* bR = bnd[(e & 1) ^ 1][(w > 0) ? (w - 1) : 0];
            float*       bW = &bnd[e & 1][w][0];

            if (lane == 31) bW[0] = f1;   // carry-in boundary

            #pragma unroll 8
            for (int k = 0; k < K_EPOCH; ++k) {
                float s2  = xs[4 * PIT + k];   // stay (log2)
                float e0v = xs[ro0 + k];
                float e1v = xs[ro1 + k];
                float bv  = bR[k];

                float up = __shfl_up_sync(0xffffffffu, f1, 1);
                float L  = up;
                if (lane == 0) L = (w == 0) ? fz : bv;

                float a0 = e0v + L;
                float a1 = e1v + f0;
                float b0 = s2 + f0;
                float b1 = s2 + f1;

                f0 = lae2(a0, b0);
                f1 = lae2(a1, b1);
                fz += s2;

                if (lane == 31 && k < K_EPOCH - 1) bW[k + 1] = f1;
            }
        }

        if (pf && tid < NFEAT * K_EPOCH) {
            float* xd = xsm + ((e + 1) & (NSLAB - 1)) * SLABP;
            int f = tid >> 5, tl = tid & 31;
            xd[f * PIT + tl] = nv0;
        }
        __syncthreads();
    }

    // write half-result to scratch. fwd: index = position. bwd: index = m = P - q.
    float* scr = fwdDir ? (g_scrF + b * (P_POS + 1)) : (g_scrB + b * (P_POS + 1));
    if (fwdDir) {
        scr[pb + 1] = f0; scr[pb + 2] = f1;
        if (tid == 0) scr[0] = fz;
    } else {
        scr[P_POS - (pb + 1)] = f0;
        scr[P_POS - (pb + 2)] = f1;
        if (tid == 0) scr[P_POS] = fz;   // q=0 -> m=P
    }
}

__global__ void __launch_bounds__(128)
ctc_combine_kernel(float* __restrict__ out)
{
    const int b    = blockIdx.x;
    const int tid  = threadIdx.x;
    const int lane = tid & 31;
    const int w    = tid >> 5;
    __shared__ float red[4];

    const float* F = g_scrF + b * (P_POS + 1);
    const float* B = g_scrB + b * (P_POS + 1);

    float vm = -3e38f;
    float v[5];
    int   nv = 0;
    for (int p = tid; p <= P_POS; p += 128) {
        float t = F[p] + B[p];
        v[nv++] = t;
        vm = fmaxf(vm, t);
    }
    #pragma unroll
    for (int off = 16; off; off >>= 1)
        vm = fmaxf(vm, __shfl_xor_sync(0xffffffffu, vm, off));
    if (lane == 0) red[w] = vm;
    __syncthreads();
    vm = fmaxf(fmaxf(red[0], red[1]), fmaxf(red[2], red[3]));

    float s = 0.f;
    for (int i = 0; i < nv; ++i) s += ex2f(v[i] - vm);
    #pragma unroll
    for (int off = 16; off; off >>= 1)
        s += __shfl_xor_sync(0xffffffffu, s, off);
    __syncthreads();
    if (lane == 0) red[w] = s;
    __syncthreads();
    if (tid == 0) {
        float st = red[0] + red[1] + red[2] + red[3];
        float lse = vm + lg2f(st);
        out[b] = -lse * (LN2F / (float)T_STEPS);
    }
}

extern "C" void kernel_launch(void* const* d_in, const int* in_sizes, int n_in,
                              void* d_out, int out_size)
{
    const float* x       = (const float*)d_in[0];
    const int*   seqs    = (const int*)  d_in[1];
    const int*   seqlens = (const int*)  d_in[2];
    float*       out     = (float*)      d_out;

    ctc_half_kernel<<<2 * BATCH, NTHREADS>>>(x, seqs, seqlens);
    ctc_combine_kernel<<<BATCH, 128>>>(out);
}

// round 10
// speedup vs baseline: 2.5557x; 1.1614x over previous
#include <cuda_runtime.h>

// CTC forward scan split at T/2 (fwd + mirrored bwd halves on separate CTAs),
// combine = -LSE_m(F[m]+B[m]) * ln2 / T.
// NEW: TWO-STEP FUSION. Per 2 time steps, position p updates once:
//   f''[p] = lae3( S2 + f[p], M1[sj(p)] + f[p-1], M2[sj(p-1),sj(p)] + f[p-2] )
// with per-step-pair coefficients staged into smem:
//   S2 (1 float), M1tab (4 floats, one lae2 each), M2tab (16 floats, adds only).
// 256 threads = 8 warps, wavefront-skewed by 32-step chunks; lane owns 2 positions.
// Per epoch: [coef compute for chunk e] -> sync -> [main 16 fused iters + raw
// prefetch of chunk e+1] -> sync.

#define T_STEPS   4096
#define T_HALF    2048
#define BATCH     64
#define NFEAT     5
#define P_POS     512
#define NEG_LARGE (-1e30f)
#define K_EPOCH   32
#define NITER     16                      // fused iterations per chunk
#define NCHUNK    (T_HALF / K_EPOCH)      // 64
#define NTHREADS  256
#define NWARPS    8
#define NEPOCH    (NCHUNK + NWARPS - 1)   // 71
#define PIT       33                      // raw slab: [feat][t] pitch
#define RSLABP    168
#define GSTRIDE   24                      // per-group coef stride: S2,M1[4],M2[16],pad
#define CSTRIDE   (NITER * GSTRIDE)       // 384 floats per coef slab
#define NCSLAB    16
#define L2E       1.4426950408889634f
#define LN2F      0.6931471805599453f

__device__ float g_scrF[BATCH * (P_POS + 1)];
__device__ float g_scrB[BATCH * (P_POS + 1)];

__device__ __forceinline__ float ex2f(float v){ float r; asm("ex2.approx.f32 %0,%1;" : "=f"(r) : "f"(v)); return r; }
__device__ __forceinline__ float lg2f(float v){ float r; asm("lg2.approx.f32 %0,%1;" : "=f"(r) : "f"(v)); return r; }

// accurate 2-MUFU logaddexp (log2 domain) — staging only
__device__ __forceinline__ float lae2(float a, float b) {
    float m = fmaxf(a, b);
    float d = -fabsf(a - b);
    return m + lg2f(1.0f + ex2f(d));
}

// 3-way logaddexp (log2 domain): sort so the max term's ex2 (==1) is skipped.
__device__ __forceinline__ float lae3(float a, float b, float c) {
    float u1 = fminf(a, b);
    float u2 = fmaxf(a, b);
    float m  = fmaxf(u2, c);
    float v  = fminf(u2, c);
    float y  = 1.0f + ex2f(u1 - m) + ex2f(v - m);
    return m + lg2f(y);
}

__global__ void __launch_bounds__(NTHREADS, 1)
ctc_half_kernel(const float* __restrict__ x,
                const int*   __restrict__ seqs,
                const int*   __restrict__ seqlens)
{
    const bool fwdDir = (blockIdx.x & 1) == 0;
    const int  b      = blockIdx.x >> 1;
    const int  tid    = threadIdx.x;
    const int  lane   = tid & 31;
    const int  w      = tid >> 5;

    __shared__ float  raw[2][RSLABP];               // raw x chunk (x * L2E), [feat][t]
    __shared__ float  cof[NCSLAB * CSTRIDE];        // fused coefs per chunk
    __shared__ float2 bnd[2][NWARPS][NITER];        // (f0,f1) of lane31 entering iter k
    __shared__ float  ffin[P_POS + 1];

    // Lane owns positions p0 = pb+1, p1 = pb+2. Emission indices (into p): sj(p)=seq-ish.
    const int pb = (w << 6) + (lane << 1);
    const int* sp = seqs + b * P_POS;
    int si0, si1, idxA;   // sj(p0), sj(p1), sj(p0-1)
    if (fwdDir) {
        si0  = sp[pb];
        si1  = sp[pb + 1];
        idxA = (pb == 0) ? 0 : sp[pb - 1];
    } else {
        si0  = sp[P_POS - 1 - pb];
        si1  = sp[P_POS - 2 - pb];
        idxA = (pb == 0) ? 0 : sp[P_POS - pb];
    }
    const int m1o0  = 1 + si0;                 // coef offsets within group
    const int m1o1  = 1 + si1;
    const int m2o0  = 5 + idxA * 4 + si0;
    const int m2o1  = 5 + si0  * 4 + si1;

    // init state: fwd -> delta at position 0 (fz); bwd -> delta at q0 = P - seqlens[b]
    const int q0 = P_POS - seqlens[b];
    float f0, f1, fz;
    if (fwdDir) {
        f0 = f1 = NEG_LARGE; fz = 0.0f;
    } else {
        f0 = (pb + 1 == q0) ? 0.f : NEG_LARGE;
        f1 = (pb + 2 == q0) ? 0.f : NEG_LARGE;
        fz = (q0 == 0) ? 0.f : NEG_LARGE;
    }

    const float* xb = x + b * NFEAT;
    const int    TB = BATCH * NFEAT;

    for (int i = tid; i < 2 * NWARPS * NITER; i += NTHREADS)
        (&bnd[0][0][0])[i] = make_float2(NEG_LARGE, NEG_LARGE);

    // prologue: raw chunk 0 -> raw[0]
    if (tid < NFEAT * K_EPOCH) {
        int f = tid >> 5, tl = tid & 31;
        int t = fwdDir ? tl : (T_STEPS - 1 - tl);
        raw[0][f * PIT + tl] = xb[t * TB + f] * L2E;
    }
    __syncthreads();

    for (int e = 0; e < NEPOCH; ++e) {
        // ---- phase 1: compute fused coefs for chunk e from raw[e&1] ----
        if (e < NCHUNK) {
            const float* rs = raw[e & 1];
            float*       cd = cof + (e & (NCSLAB - 1)) * CSTRIDE;
            const int g = tid >> 4;        // group 0..15 (2 steps each)
            const int j = tid & 15;
            const int t0 = 2 * g, t1 = 2 * g + 1;
            float st0 = rs[4 * PIT + t0];
            float st1 = rs[4 * PIT + t1];
            float* gb = cd + g * GSTRIDE;
            if (j == 0) {
                gb[0] = st0 + st1;                         // S2
            } else if (j <= 4) {
                int jj = j - 1;                            // M1tab[jj]
                gb[1 + jj] = lae2(rs[jj * PIT + t0] + st1, st0 + rs[jj * PIT + t1]);
            } else {
                int ei = j - 5;                            // M2 entries 0..10
                gb[5 + ei] = rs[(ei >> 2) * PIT + t0] + rs[(ei & 3) * PIT + t1];
            }
            if (j <= 4 && j >= 1) {                        // M2 entries 11..15
                int ei = 10 + j;
                gb[5 + ei] = rs[(ei >> 2) * PIT + t0] + rs[(ei & 3) * PIT + t1];
            }
        }
        __syncthreads();

        const int  c     = e - w;
        const bool valid = (c >= 0) && (c < NCHUNK);

        // prefetch raw chunk e+1 into registers
        float nv0 = 0.f;
        const bool pf = (e + 1) < NCHUNK;
        if (pf && tid < NFEAT * K_EPOCH) {
            const int s0 = (e + 1) * K_EPOCH;
            int f = tid >> 5, tl = tid & 31;
            int tg = fwdDir ? (s0 + tl) : (T_STEPS - 1 - (s0 + tl));
            nv0 = xb[tg * TB + f] * L2E;
        }

        if (valid) {
            const float*  cs = cof + (c & (NCSLAB - 1)) * CSTRIDE;
            const float2* bR = bnd[(e & 1) ^ 1][(w > 0) ? (w - 1) : 0];
            float2*       bW = &bnd[e & 1][w][0];

            #pragma unroll
            for (int k = 0; k < NITER; ++k) {
                const float* gb  = cs + k * GSTRIDE;
                float S2  = gb[0];
                float M1a = gb[m1o0];
                float M1b = gb[m1o1];
                float M2a = gb[m2o0];
                float M2b = gb[m2o1];
                float2 bv = bR[k];

                float Lf0 = __shfl_up_sync(0xffffffffu, f0, 1);
                float Lf1 = __shfl_up_sync(0xffffffffu, f1, 1);
                if (lane == 0) {
                    Lf0 = (w == 0) ? NEG_LARGE : bv.x;
                    Lf1 = (w == 0) ? fz        : bv.y;
                }
                if (lane == 31) bW[k] = make_float2(f0, f1);

                float a0 = S2 + f0;
                float b0 = M1a + Lf1;
                float c0 = M2a + Lf0;
                float a1 = S2 + f1;
                float b1 = M1b + f0;     // old f0
                float c1 = M2b + Lf1;
                fz += S2;

                f0 = lae3(a0, b0, c0);
                f1 = lae3(a1, b1, c1);
            }
        }

        // commit prefetched raw chunk
        if (pf && tid < NFEAT * K_EPOCH) {
            int f = tid >> 5, tl = tid & 31;
            raw[(e + 1) & 1][f * PIT + tl] = nv0;
        }
        __syncthreads();
    }

    // epilogue: gather fwd[seqlens[b]] material. fwd: index = position; bwd: m = P - q.
    float* scr = fwdDir ? (g_scrF + b * (P_POS + 1)) : (g_scrB + b * (P_POS + 1));
    if (fwdDir) {
        scr[pb + 1] = f0; scr[pb + 2] = f1;
        if (tid == 0) scr[0] = fz;
    } else {
        scr[P_POS - (pb + 1)] = f0;
        scr[P_POS - (pb + 2)] = f1;
        if (tid == 0) scr[P_POS] = fz;
    }
}

__global__ void __launch_bounds__(128)
ctc_combine_kernel(float* __restrict__ out)
{
    const int b    = blockIdx.x;
    const int tid  = threadIdx.x;
    const int lane = tid & 31;
    const int w    = tid >> 5;
    __shared__ float red[4];

    const float* F = g_scrF + b * (P_POS + 1);
    const float* B = g_scrB + b * (P_POS + 1);

    float vm = -3e38f;
    float v[5];
    int   nv = 0;
    for (int p = tid; p <= P_POS; p += 128) {
        float t = F[p] + B[p];
        v[nv++] = t;
        vm = fmaxf(vm, t);
    }
    #pragma unroll
    for (int off = 16; off; off >>= 1)
        vm = fmaxf(vm, __shfl_xor_sync(0xffffffffu, vm, off));
    if (lane == 0) red[w] = vm;
    __syncthreads();
    vm = fmaxf(fmaxf(red[0], red[1]), fmaxf(red[2], red[3]));

    float s = 0.f;
    for (int i = 0; i < nv; ++i) s += ex2f(v[i] - vm);
    #pragma unroll
    for (int off = 16; off; off >>= 1)
        s += __shfl_xor_sync(0xffffffffu, s, off);
    __syncthreads();
    if (lane == 0) red[w] = s;
    __syncthreads();
    if (tid == 0) {
        float st = red[0] + red[1] + red[2] + red[3];
        float lse = vm + lg2f(st);
        out[b] = -lse * (LN2F / (float)T_STEPS);
    }
}

extern "C" void kernel_launch(void* const* d_in, const int* in_sizes, int n_in,
                              void* d_out, int out_size)
{
    const float* x       = (const float*)d_in[0];
    const int*   seqs    = (const int*)  d_in[1];
    const int*   seqlens = (const int*)  d_in[2];
    float*       out     = (float*)      d_out;

    ctc_half_kernel<<<2 * BATCH, NTHREADS>>>(x, seqs, seqlens);
    ctc_combine_kernel<<<BATCH, 128>>>(out);
}

// round 11
// speedup vs baseline: 3.0816x; 1.2058x over previous
#include <cuda_runtime.h>

// CTC forward scan split at T/2 (fwd + mirrored bwd halves on separate CTAs),
// combine = -LSE_m(F[m]+B[m]) * ln2 / T.
// TWO-STEP FUSION: f''[p] = lae3(S2+f[p], M1[sj(p)]+f[p-1], M2[sj(p-1),sj(p)]+f[p-2]).
// Coefs (S2, M1[4], M2[16]) per step-pair staged in a 16-slab smem ring.
// NEW vs R10: (a) M2[15] staging hole fixed (all 21 entries written),
// (b) coef staging sources x straight from gmem registers (LDGs issued at epoch
//     start, consumed at epoch end) -> raw smem slab gone, ONE barrier per epoch,
// (c) fz maintained by warp 0 only.

#define T_STEPS   4096
#define T_HALF    2048
#define BATCH     64
#define NFEAT     5
#define P_POS     512
#define NEG_LARGE (-1e30f)
#define K_EPOCH   32
#define NITER     16                      // fused iterations per chunk
#define NCHUNK    (T_HALF / K_EPOCH)      // 64
#define NTHREADS  256
#define NWARPS    8
#define NEPOCH    (NCHUNK + NWARPS - 1)   // 71
#define GSTRIDE   24                      // S2, M1[4], M2[16], pad
#define CSTRIDE   (NITER * GSTRIDE)       // 384 floats per chunk slab
#define NCSLAB    16
#define L2E       1.4426950408889634f
#define LN2F      0.6931471805599453f

__device__ float g_scrF[BATCH * (P_POS + 1)];
__device__ float g_scrB[BATCH * (P_POS + 1)];

__device__ __forceinline__ float ex2f(float v){ float r; asm("ex2.approx.f32 %0,%1;" : "=f"(r) : "f"(v)); return r; }
__device__ __forceinline__ float lg2f(float v){ float r; asm("lg2.approx.f32 %0,%1;" : "=f"(r) : "f"(v)); return r; }

// accurate 2-MUFU logaddexp (log2 domain) — staging only
__device__ __forceinline__ float lae2(float a, float b) {
    float m = fmaxf(a, b);
    float d = -fabsf(a - b);
    return m + lg2f(1.0f + ex2f(d));
}

// 3-way logaddexp (log2 domain): max term's ex2 (==1) skipped via sort.
__device__ __forceinline__ float lae3(float a, float b, float c) {
    float u1 = fminf(a, b);
    float u2 = fmaxf(a, b);
    float m  = fmaxf(u2, c);
    float v  = fminf(u2, c);
    float y  = 1.0f + (ex2f(u1 - m) + ex2f(v - m));
    return m + lg2f(y);
}

__global__ void __launch_bounds__(NTHREADS, 1)
ctc_half_kernel(const float* __restrict__ x,
                const int*   __restrict__ seqs,
                const int*   __restrict__ seqlens)
{
    const bool fwdDir = (blockIdx.x & 1) == 0;
    const int  b      = blockIdx.x >> 1;
    const int  tid    = threadIdx.x;
    const int  lane   = tid & 31;
    const int  w      = tid >> 5;

    __shared__ float  cof[NCSLAB * CSTRIDE];   // fused coefs per chunk (ring)
    __shared__ float2 bnd[2][NWARPS][NITER];   // lane31 (f0,f1) entering iter k

    const float* xb = x + b * NFEAT;           // x[t*B*F + b*F + f]
    const int    TB = BATCH * NFEAT;

    // ---- per-thread coef staging assignment (fixed): group g, slot j ----
    // out0 -> gb[j]:  j==0: S2 | j in 1..4: M1[j-1] | j in 5..15: M2[j-5]
    // out1 -> gb[16+j] (j<=4 only): M2[11+j]
    const int g  = tid >> 4;
    const int j  = tid & 15;
    const bool hasOut1 = (j <= 4);
    // feature indices for out0 loads (a0 @ step s0, a1 @ step s1):
    int fa0, fa1; bool isM1 = false, isS2 = false;
    if (j == 0)      { fa0 = 4; fa1 = 4; isS2 = true; }
    else if (j <= 4) { fa0 = j - 1; fa1 = j - 1; isM1 = true; }
    else             { int ei = j - 5; fa0 = ei >> 2; fa1 = ei & 3; }
    // out1 loads (M2[11+j]): row=(11+j)>>2, col=(11+j)&3
    const int fb0 = (11 + j) >> 2;
    const int fb1 = (11 + j) & 3;

    // ---- per-lane recurrence setup ----
    const int pb = (w << 6) + (lane << 1);     // lane owns positions pb+1, pb+2
    const int* sp = seqs + b * P_POS;
    int si0, si1, idxA;                        // sj(p0), sj(p1), sj(p0-1)
    if (fwdDir) {
        si0  = sp[pb];
        si1  = sp[pb + 1];
        idxA = (pb == 0) ? 0 : sp[pb - 1];
    } else {
        si0  = sp[P_POS - 1 - pb];
        si1  = sp[P_POS - 2 - pb];
        idxA = (pb == 0) ? 0 : sp[P_POS - pb];
    }
    const int m1o0 = 1 + si0;
    const int m1o1 = 1 + si1;
    const int m2o0 = 5 + idxA * 4 + si0;
    const int m2o1 = 5 + si0  * 4 + si1;

    const int q0 = P_POS - seqlens[b];
    float f0, f1, fz;
    if (fwdDir) {
        f0 = f1 = NEG_LARGE; fz = 0.0f;
    } else {
        f0 = (pb + 1 == q0) ? 0.f : NEG_LARGE;
        f1 = (pb + 2 == q0) ? 0.f : NEG_LARGE;
        fz = (q0 == 0) ? 0.f : NEG_LARGE;
    }

    for (int i = tid; i < 2 * NWARPS * NITER; i += NTHREADS)
        (&bnd[0][0][0])[i] = make_float2(NEG_LARGE, NEG_LARGE);

    // gmem step index for (chunk cc, local step sl): s = cc*32+sl; t-map per direction
    #define GTIME(s) (fwdDir ? (s) : (T_STEPS - 1 - (s)))

    // ---- prologue: stage coefs for chunk 0 into slab 0 ----
    {
        const int s0 = 2 * g, s1 = 2 * g + 1;
        const long o0 = (long)GTIME(s0) * TB, o1 = (long)GTIME(s1) * TB;
        float a0 = xb[o0 + fa0] * L2E;
        float a1 = xb[o1 + fa1] * L2E;
        float st0 = 0.f, st1 = 0.f, b0v = 0.f, b1v = 0.f;
        if (isM1) { st0 = xb[o0 + 4] * L2E; st1 = xb[o1 + 4] * L2E; }
        if (hasOut1) { b0v = xb[o0 + fb0] * L2E; b1v = xb[o1 + fb1] * L2E; }
        float* gb = cof + g * GSTRIDE;
        gb[j] = isM1 ? lae2(a0 + st1, st0 + a1) : (a0 + a1);
        if (hasOut1) gb[16 + j] = b0v + b1v;
    }
    __syncthreads();

    for (int e = 0; e < NEPOCH; ++e) {
        // ---- issue LDGs for chunk e+1 coef inputs (hidden under compute) ----
        float a0 = 0.f, a1 = 0.f, st0 = 0.f, st1 = 0.f, b0v = 0.f, b1v = 0.f;
        const bool pf = (e + 1) < NCHUNK;
        if (pf) {
            const int s0 = (e + 1) * K_EPOCH + 2 * g, s1 = s0 + 1;
            const long o0 = (long)GTIME(s0) * TB, o1 = (long)GTIME(s1) * TB;
            a0 = xb[o0 + fa0] * L2E;
            a1 = xb[o1 + fa1] * L2E;
            if (isM1) { st0 = xb[o0 + 4] * L2E; st1 = xb[o1 + 4] * L2E; }
            if (hasOut1) { b0v = xb[o0 + fb0] * L2E; b1v = xb[o1 + fb1] * L2E; }
        }

        const int  c     = e - w;
        const bool valid = (c >= 0) && (c < NCHUNK);

        if (valid) {
            const float*  cs = cof + (c & (NCSLAB - 1)) * CSTRIDE;
            const float2* bR = bnd[(e & 1) ^ 1][(w > 0) ? (w - 1) : 0];
            float2*       bW = &bnd[e & 1][w][0];

            #pragma unroll
            for (int k = 0; k < NITER; ++k) {
                const float* gb  = cs + k * GSTRIDE;
                float S2  = gb[0];
                float M1a = gb[m1o0];
                float M1b = gb[m1o1];
                float M2a = gb[m2o0];
                float M2b = gb[m2o1];
                float2 bv = bR[k];

                float Lf0 = __shfl_up_sync(0xffffffffu, f0, 1);
                float Lf1 = __shfl_up_sync(0xffffffffu, f1, 1);
                if (lane == 0) {
                    Lf0 = (w == 0) ? NEG_LARGE : bv.x;
                    Lf1 = (w == 0) ? fz        : bv.y;
                }
                if (lane == 31) bW[k] = make_float2(f0, f1);

                float A0 = S2 + f0;
                float B0 = M1a + Lf1;
                float C0 = M2a + Lf0;
                float A1 = S2 + f1;
                float B1 = M1b + f0;     // old f0
                float C1 = M2b + Lf1;
                if (w == 0) fz += S2;

                f0 = lae3(A0, B0, C0);
                f1 = lae3(A1, B1, C1);
            }
        }

        // ---- compute + commit coefs for chunk e+1 ----
        if (pf) {
            float* gb = cof + ((e + 1) & (NCSLAB - 1)) * CSTRIDE + g * GSTRIDE;
            gb[j] = isM1 ? lae2(a0 + st1, st0 + a1) : (a0 + a1);
            if (hasOut1) gb[16 + j] = b0v + b1v;
        }
        __syncthreads();
    }

    // ---- epilogue: write half-result. fwd: index = position; bwd: m = P - q. ----
    float* scr = fwdDir ? (g_scrF + b * (P_POS + 1)) : (g_scrB + b * (P_POS + 1));
    if (fwdDir) {
        scr[pb + 1] = f0; scr[pb + 2] = f1;
        if (tid == 0) scr[0] = fz;
    } else {
        scr[P_POS - (pb + 1)] = f0;
        scr[P_POS - (pb + 2)] = f1;
        if (tid == 0) scr[P_POS] = fz;
    }
}

__global__ void __launch_bounds__(128)
ctc_combine_kernel(float* __restrict__ out)
{
    const int b    = blockIdx.x;
    const int tid  = threadIdx.x;
    const int lane = tid & 31;
    const int w    = tid >> 5;
    __shared__ float red[4];

    const float* F = g_scrF + b * (P_POS + 1);
    const float* B = g_scrB + b * (P_POS + 1);

    float vm = -3e38f;
    float v[5];
    int   nv = 0;
    for (int p = tid; p <= P_POS; p += 128) {
        float t = F[p] + B[p];
        v[nv++] = t;
        vm = fmaxf(vm, t);
    }
    #pragma unroll
    for (int off = 16; off; off >>= 1)
        vm = fmaxf(vm, __shfl_xor_sync(0xffffffffu, vm, off));
    if (lane == 0) red[w] = vm;
    __syncthreads();
    vm = fmaxf(fmaxf(red[0], red[1]), fmaxf(red[2], red[3]));

    float s = 0.f;
    for (int i = 0; i < nv; ++i) s += ex2f(v[i] - vm);
    #pragma unroll
    for (int off = 16; off; off >>= 1)
        s += __shfl_xor_sync(0xffffffffu, s, off);
    __syncthreads();
    if (lane == 0) red[w] = s;
    __syncthreads();
    if (tid == 0) {
        float st = red[0] + red[1] + red[2] + red[3];
        float lse = vm + lg2f(st);
        out[b] = -lse * (LN2F / (float)T_STEPS);
    }
}

extern "C" void kernel_launch(void* const* d_in, const int* in_sizes, int n_in,
                              void* d_out, int out_size)
{
    const float* x       = (const float*)d_in[0];
    const int*   seqs    = (const int*)  d_in[1];
    const int*   seqlens = (const int*)  d_in[2];
    float*       out     = (float*)      d_out;

    ctc_half_kernel<<<2 * BATCH, NTHREADS>>>(x, seqs, seqlens);
    ctc_combine_kernel<<<BATCH, 128>>>(out);
}